// round 7
// baseline (speedup 1.0000x reference)
#include <cuda_runtime.h>
#include <cuda_fp16.h>

#define N_NODES 50000
#define N_FEAT  128
#define N_EDGES 600000
#define N_POWERS 3

// fp16 staging copy of x (halves gather traffic + L1 wavefronts).
__device__ __half g_x16[(size_t)N_NODES * N_FEAT];

// 1 if edge_index is genuinely int64 on device, 0 if int32 (JAX x64-off).
__device__ int g_idx_is64;

__global__ void __launch_bounds__(256)
convert_x_kernel(const float* __restrict__ x, const int* __restrict__ ei32)
{
    if (blockIdx.x == 0 && threadIdx.x == 0) {
        int all_zero = 1;
#pragma unroll
        for (int k = 1; k < 256; k += 2) all_zero &= (ei32[k] == 0);
        g_idx_is64 = all_zero;
    }
    const int i = (blockIdx.x * blockDim.x + threadIdx.x) * 4;
    if (i < N_NODES * N_FEAT) {
        const float4 v = *reinterpret_cast<const float4*>(x + i);
        __half2 h0 = __floats2half2_rn(v.x, v.y);
        __half2 h1 = __floats2half2_rn(v.z, v.w);
        uint2 packed;
        packed.x = *reinterpret_cast<unsigned*>(&h0);
        packed.y = *reinterpret_cast<unsigned*>(&h1);
        *reinterpret_cast<uint2*>(&g_x16[i]) = packed;
    }
}

// abs via sign-mask (LOP3 on alu pipe instead of HABS2 on fma pipe).
static __device__ __forceinline__ __half2 habs2_and(__half2 v) {
    unsigned u = *reinterpret_cast<unsigned*>(&v) & 0x7FFF7FFFu;
    return *reinterpret_cast<__half2*>(&u);
}

// Fold half2 -> float (sum of both halves): PRMT(alu) + HADD2(fma) + 1 cvt.
static __device__ __forceinline__ float hfold(__half2 a) {
    return __low2float(__hadd2(a, __lowhigh2highlow(a)));
}

struct Buf {
    __half2 jA[8], iA[8], jB[8], iB[8];
};

struct Idx { int sA, dA, sB, dB; };

static __device__ __forceinline__ Idx load_idx(
    const int* ei32, const long long* ei64, int is64,
    size_t src_base, size_t dst_base, int si, int g)
{
    Idx I;
    const int eA = si * 8 + g, eB = eA + 4;
    if (is64) {
        I.sA = (int)ei64[src_base + eA]; I.dA = (int)ei64[dst_base + eA];
        I.sB = (int)ei64[src_base + eB]; I.dB = (int)ei64[dst_base + eB];
    } else {
        I.sA = ei32[src_base + eA]; I.dA = ei32[dst_base + eA];
        I.sB = ei32[src_base + eB]; I.dB = ei32[dst_base + eB];
    }
    return I;
}

static __device__ __forceinline__ void load_buf(Buf& b, const Idx& I, int fA, int fB)
{
    const __half* rjA = &g_x16[(size_t)I.sA * N_FEAT];
    const __half* riA = &g_x16[(size_t)I.dA * N_FEAT];
    const __half* rjB = &g_x16[(size_t)I.sB * N_FEAT];
    const __half* riB = &g_x16[(size_t)I.dB * N_FEAT];
    *reinterpret_cast<uint4*>(&b.jA[0]) = *reinterpret_cast<const uint4*>(rjA + fA);
    *reinterpret_cast<uint4*>(&b.jA[4]) = *reinterpret_cast<const uint4*>(rjA + fB);
    *reinterpret_cast<uint4*>(&b.iA[0]) = *reinterpret_cast<const uint4*>(riA + fA);
    *reinterpret_cast<uint4*>(&b.iA[4]) = *reinterpret_cast<const uint4*>(riA + fB);
    *reinterpret_cast<uint4*>(&b.jB[0]) = *reinterpret_cast<const uint4*>(rjB + fA);
    *reinterpret_cast<uint4*>(&b.jB[4]) = *reinterpret_cast<const uint4*>(rjB + fB);
    *reinterpret_cast<uint4*>(&b.iB[0]) = *reinterpret_cast<const uint4*>(riB + fA);
    *reinterpret_cast<uint4*>(&b.iB[4]) = *reinterpret_cast<const uint4*>(riB + fB);
}

// Compute 8 edges from buffer, reduce, epilogue, coalesced store.
static __device__ __forceinline__ void compute_store(
    const Buf& b, const __half2 w2[3][8],
    float ba0, float ba1, float ba2,
    float wb0, float wb1, float wb2, float bbv,
    float* outp, int si, int lane)
{
    __half2 a0A = __float2half2_rn(0.f), a1A = a0A, a2A = a0A;
    __half2 a0B = a0A, a1B = a0A, a2B = a0A;
#pragma unroll
    for (int k = 0; k < 8; ++k) {
        const __half2 dhA = habs2_and(__hsub2(b.jA[k], b.iA[k]));
        const __half2 dhB = habs2_and(__hsub2(b.jB[k], b.iB[k]));
        a0A = __hfma2(dhA, w2[0][k], a0A);
        a0B = __hfma2(dhB, w2[0][k], a0B);
        a1A = __hfma2(dhA, w2[1][k], a1A);
        a1B = __hfma2(dhB, w2[1][k], a1B);
        a2A = __hfma2(dhA, w2[2][k], a2A);
        a2B = __hfma2(dhB, w2[2][k], a2B);
    }

    const float x0A = hfold(a0A), x1A = hfold(a1A), x2A = hfold(a2A);
    const float x0B = hfold(a0B), x1B = hfold(a1B), x2B = hfold(a2B);

    // Interleaved A/B butterfly: even lanes accumulate A, odd lanes B.
    // Step 1 (off=1) merges A into evens / B into odds; steps 2,4 reduce
    // within the parity class. Exact fp32.
    const bool odd = (lane & 1);
    float t0 = odd ? x0B : x0A;
    float u0 = odd ? x0A : x0B;
    float t1 = odd ? x1B : x1A;
    float u1 = odd ? x1A : x1B;
    float t2 = odd ? x2B : x2A;
    float u2 = odd ? x2A : x2B;
    t0 += __shfl_xor_sync(0xFFFFFFFFu, u0, 1);
    t1 += __shfl_xor_sync(0xFFFFFFFFu, u1, 1);
    t2 += __shfl_xor_sync(0xFFFFFFFFu, u2, 1);
#pragma unroll
    for (int off = 2; off <= 4; off <<= 1) {
        t0 += __shfl_xor_sync(0xFFFFFFFFu, t0, off);
        t1 += __shfl_xor_sync(0xFFFFFFFFu, t1, off);
        t2 += __shfl_xor_sync(0xFFFFFFFFu, t2, off);
    }
    // Now every even lane of group g holds A_g sums; every odd lane B_g.

    // Route edge lane: lane L (0..7) takes edge L: A_g for L<4 (src even lane
    // 8*(L&3)), B_g for L>=4 (src odd lane 8*(L&3)+1).
    const int src = ((lane & 3) << 3) | ((lane & 4) >> 2);
    const float y0 = __shfl_sync(0xFFFFFFFFu, t0, src);
    const float y1 = __shfl_sync(0xFFFFFFFFu, t1, src);
    const float y2 = __shfl_sync(0xFFFFFFFFu, t2, src);

    const float h0 = fmaxf(y0 + ba0, 0.f);
    const float h1 = fmaxf(y1 + ba1, 0.f);
    const float h2 = fmaxf(y2 + ba2, 0.f);
    const float z  = h0 * wb0 + h1 * wb1 + h2 * wb2 + bbv;
    const float r  = 1.0f / (1.0f + __expf(-z));
    if (lane < 8) outp[si * 8 + lane] = r;
}

// 8 lanes per edge, 8 edges per warp-iteration, cross-iteration double
// buffering of the gathered rows (each warp hides its own gather latency).
__global__ void __launch_bounds__(128, 4)
adj_learn_kernel(const void* __restrict__ edge_index_raw,
                 const float* __restrict__ Wa,
                 const float* __restrict__ ba,
                 const float* __restrict__ Wb,
                 const float* __restrict__ bb,
                 float* __restrict__ out)
{
    const int p    = blockIdx.y;
    const int lane = threadIdx.x & 31;
    const int l    = lane & 7;
    const int g    = lane >> 3;
    const int warp = threadIdx.x >> 5;
    const int warps_per_block = blockDim.x >> 5;
    const int gwarp  = blockIdx.x * warps_per_block + warp;
    const int nwarps = gridDim.x * warps_per_block;

    const int is64 = g_idx_is64;

    const int fA = l * 8;
    const int fB = 64 + l * 8;

    const float* Wap = Wa + (size_t)p * (N_FEAT * 3);
    __half2 w2[3][8];
#pragma unroll
    for (int k = 0; k < 4; ++k) {
#pragma unroll
        for (int h = 0; h < 3; ++h) {
            w2[h][k]     = __floats2half2_rn(Wap[(fA + 2 * k) * 3 + h],
                                             Wap[(fA + 2 * k + 1) * 3 + h]);
            w2[h][k + 4] = __floats2half2_rn(Wap[(fB + 2 * k) * 3 + h],
                                             Wap[(fB + 2 * k + 1) * 3 + h]);
        }
    }
    const float ba0 = ba[p * 3 + 0];
    const float ba1 = ba[p * 3 + 1];
    const float ba2 = ba[p * 3 + 2];
    const float wb0 = Wb[p * 3 + 0];
    const float wb1 = Wb[p * 3 + 1];
    const float wb2 = Wb[p * 3 + 2];
    const float bbv = bb[p];

    const int*       ei32 = (const int*)edge_index_raw;
    const long long* ei64 = (const long long*)edge_index_raw;
    const size_t src_base = (size_t)p * 2 * N_EDGES;
    const size_t dst_base = src_base + N_EDGES;
    float* outp = out + (size_t)p * N_EDGES;

    const int n_sup = N_EDGES / 8;    // 75000
    const int st = nwarps;

    int pi = gwarp;
    if (pi >= n_sup) return;

    Buf b0, b1;
    Idx Icur = load_idx(ei32, ei64, is64, src_base, dst_base, pi, g);
    load_buf(b0, Icur, fA, fB);

    int p1 = pi + st;
    Idx I1;
    if (p1 < n_sup) I1 = load_idx(ei32, ei64, is64, src_base, dst_base, p1, g);

    while (true) {
        // Phase 0: data(pi) in b0. Load p1 into b1, prefetch idx(p2).
        {
            if (p1 < n_sup) load_buf(b1, I1, fA, fB);
            const int p2 = p1 + st;
            Idx I2;
            if (p2 < n_sup) I2 = load_idx(ei32, ei64, is64, src_base, dst_base, p2, g);
            compute_store(b0, w2, ba0, ba1, ba2, wb0, wb1, wb2, bbv, outp, pi, lane);
            pi = p1; p1 = p2; I1 = I2;
        }
        if (pi >= n_sup) break;
        // Phase 1: data(pi) in b1. Load p1 into b0.
        {
            if (p1 < n_sup) load_buf(b0, I1, fA, fB);
            const int p2 = p1 + st;
            Idx I2;
            if (p2 < n_sup) I2 = load_idx(ei32, ei64, is64, src_base, dst_base, p2, g);
            compute_store(b1, w2, ba0, ba1, ba2, wb0, wb1, wb2, bbv, outp, pi, lane);
            pi = p1; p1 = p2; I1 = I2;
        }
        if (pi >= n_sup) break;
    }
}

extern "C" void kernel_launch(void* const* d_in, const int* in_sizes, int n_in,
                              void* d_out, int out_size)
{
    const float* x  = (const float*)d_in[0];
    const void*  ei = d_in[1];
    const float* Wa = (const float*)d_in[2];
    const float* ba = (const float*)d_in[3];
    const float* Wb = (const float*)d_in[4];
    const float* bb = (const float*)d_in[5];
    float* out = (float*)d_out;

    convert_x_kernel<<<(N_NODES * N_FEAT / 4 + 255) / 256, 256>>>(x, (const int*)ei);

    // 588 blocks total = 4 CTAs/SM x 147 SMs -> a single wave.
    dim3 grid(196, N_POWERS, 1);
    dim3 block(128, 1, 1);
    adj_learn_kernel<<<grid, block>>>(ei, Wa, ba, Wb, bb, out);
}

// round 8
// speedup vs baseline: 1.1171x; 1.1171x over previous
#include <cuda_runtime.h>
#include <cuda_fp16.h>

#define N_NODES 50000
#define N_FEAT  128
#define N_EDGES 600000
#define N_POWERS 3

// fp16 staging copy of x (halves gather traffic + L1 wavefronts).
__device__ __half g_x16[(size_t)N_NODES * N_FEAT];

// 1 if edge_index is genuinely int64 on device, 0 if int32 (JAX x64-off).
__device__ int g_idx_is64;

__global__ void __launch_bounds__(256)
convert_x_kernel(const float* __restrict__ x, const int* __restrict__ ei32)
{
    if (blockIdx.x == 0 && threadIdx.x == 0) {
        int all_zero = 1;
#pragma unroll
        for (int k = 1; k < 256; k += 2) all_zero &= (ei32[k] == 0);
        g_idx_is64 = all_zero;
    }
    const int i = (blockIdx.x * blockDim.x + threadIdx.x) * 4;
    if (i < N_NODES * N_FEAT) {
        const float4 v = *reinterpret_cast<const float4*>(x + i);
        __half2 h0 = __floats2half2_rn(v.x, v.y);
        __half2 h1 = __floats2half2_rn(v.z, v.w);
        uint2 packed;
        packed.x = *reinterpret_cast<unsigned*>(&h0);
        packed.y = *reinterpret_cast<unsigned*>(&h1);
        *reinterpret_cast<uint2*>(&g_x16[i]) = packed;
    }
}

// abs via sign-mask (LOP3 on alu pipe instead of HABS2 on fma pipe).
static __device__ __forceinline__ __half2 habs2_and(__half2 v) {
    unsigned u = *reinterpret_cast<unsigned*>(&v) & 0x7FFF7FFFu;
    return *reinterpret_cast<__half2*>(&u);
}

// Fold half2 -> float (sum of both halves): PRMT(alu) + HADD2(fma) + 1 cvt.
static __device__ __forceinline__ float hfold(__half2 a) {
    return __low2float(__hadd2(a, __lowhigh2highlow(a)));
}

// 8 lanes per edge, 8 edges per warp-iteration (sub-groups A/B of adjacent
// edges). Lane l owns two contiguous 16B chunks per row: features [8l,8l+8)
// and [64+8l,64+8l+8) -> each warp LDG.128 covers exactly one 128B line per
// edge-row. All 8 gathers issue before any compute. Layer-1 in half2 HFMA2;
// parity-interleaved fp32 butterfly (9 SHFL); single merged epilogue with
// MUFU.RCP sigmoid and one coalesced 32B store.
__global__ void __launch_bounds__(256, 3)
adj_learn_kernel(const void* __restrict__ edge_index_raw,
                 const float* __restrict__ Wa,
                 const float* __restrict__ ba,
                 const float* __restrict__ Wb,
                 const float* __restrict__ bb,
                 float* __restrict__ out)
{
    const int p    = blockIdx.y;
    const int lane = threadIdx.x & 31;
    const int l    = lane & 7;        // lane within edge-group
    const int g    = lane >> 3;       // sub-group edge slot 0..3
    const int warp = threadIdx.x >> 5;
    const int warps_per_block = blockDim.x >> 5;
    const int gwarp  = blockIdx.x * warps_per_block + warp;
    const int nwarps = gridDim.x * warps_per_block;

    const int is64 = g_idx_is64;

    // Lane's two feature blocks (8 features each).
    const int fA = l * 8;
    const int fB = 64 + l * 8;

    // Per-lane weights: half2 feature-pairs, k=0..3 -> block A, k=4..7 -> block B.
    const float* Wap = Wa + (size_t)p * (N_FEAT * 3);
    __half2 w2[3][8];
#pragma unroll
    for (int k = 0; k < 4; ++k) {
#pragma unroll
        for (int h = 0; h < 3; ++h) {
            w2[h][k]     = __floats2half2_rn(Wap[(fA + 2 * k) * 3 + h],
                                             Wap[(fA + 2 * k + 1) * 3 + h]);
            w2[h][k + 4] = __floats2half2_rn(Wap[(fB + 2 * k) * 3 + h],
                                             Wap[(fB + 2 * k + 1) * 3 + h]);
        }
    }
    const float ba0 = ba[p * 3 + 0];
    const float ba1 = ba[p * 3 + 1];
    const float ba2 = ba[p * 3 + 2];
    const float wb0 = Wb[p * 3 + 0];
    const float wb1 = Wb[p * 3 + 1];
    const float wb2 = Wb[p * 3 + 2];
    const float bbv = bb[p];

    const int*       ei32 = (const int*)edge_index_raw;
    const long long* ei64 = (const long long*)edge_index_raw;
    const size_t src_base = (size_t)p * 2 * N_EDGES;
    const size_t dst_base = src_base + N_EDGES;
    float* outp = out + (size_t)p * N_EDGES;

    const int n_sup = N_EDGES / 8;    // 75000 super-groups of 8 edges

    int si = gwarp;
    int sA = 0, dA = 0, sB = 0, dB = 0;
    if (si < n_sup) {
        const int eA = si * 8 + g, eB = eA + 4;
        if (is64) {
            sA = (int)ei64[src_base + eA]; dA = (int)ei64[dst_base + eA];
            sB = (int)ei64[src_base + eB]; dB = (int)ei64[dst_base + eB];
        } else {
            sA = ei32[src_base + eA]; dA = ei32[dst_base + eA];
            sB = ei32[src_base + eB]; dB = ei32[dst_base + eB];
        }
    }

    while (si < n_sup) {
        // Prefetch next super-group's indices.
        const int sn = si + nwarps;
        int sAn = 0, dAn = 0, sBn = 0, dBn = 0;
        if (sn < n_sup) {
            const int eA = sn * 8 + g, eB = eA + 4;
            if (is64) {
                sAn = (int)ei64[src_base + eA]; dAn = (int)ei64[dst_base + eA];
                sBn = (int)ei64[src_base + eB]; dBn = (int)ei64[dst_base + eB];
            } else {
                sAn = ei32[src_base + eA]; dAn = ei32[dst_base + eA];
                sBn = ei32[src_base + eB]; dBn = ei32[dst_base + eB];
            }
        }

        // Issue all 8 gathers before any compute.
        const __half* rjA = &g_x16[(size_t)sA * N_FEAT];
        const __half* riA = &g_x16[(size_t)dA * N_FEAT];
        const __half* rjB = &g_x16[(size_t)sB * N_FEAT];
        const __half* riB = &g_x16[(size_t)dB * N_FEAT];

        __half2 jvA[8], ivA[8], jvB[8], ivB[8];
        *reinterpret_cast<uint4*>(&jvA[0]) = *reinterpret_cast<const uint4*>(rjA + fA);
        *reinterpret_cast<uint4*>(&jvA[4]) = *reinterpret_cast<const uint4*>(rjA + fB);
        *reinterpret_cast<uint4*>(&ivA[0]) = *reinterpret_cast<const uint4*>(riA + fA);
        *reinterpret_cast<uint4*>(&ivA[4]) = *reinterpret_cast<const uint4*>(riA + fB);
        *reinterpret_cast<uint4*>(&jvB[0]) = *reinterpret_cast<const uint4*>(rjB + fA);
        *reinterpret_cast<uint4*>(&jvB[4]) = *reinterpret_cast<const uint4*>(rjB + fB);
        *reinterpret_cast<uint4*>(&ivB[0]) = *reinterpret_cast<const uint4*>(riB + fA);
        *reinterpret_cast<uint4*>(&ivB[4]) = *reinterpret_cast<const uint4*>(riB + fB);

        __half2 a0A = __float2half2_rn(0.f), a1A = a0A, a2A = a0A;
        __half2 a0B = a0A, a1B = a0A, a2B = a0A;
#pragma unroll
        for (int k = 0; k < 8; ++k) {
            const __half2 dhA = habs2_and(__hsub2(jvA[k], ivA[k]));
            const __half2 dhB = habs2_and(__hsub2(jvB[k], ivB[k]));
            a0A = __hfma2(dhA, w2[0][k], a0A);
            a0B = __hfma2(dhB, w2[0][k], a0B);
            a1A = __hfma2(dhA, w2[1][k], a1A);
            a1B = __hfma2(dhB, w2[1][k], a1B);
            a2A = __hfma2(dhA, w2[2][k], a2A);
            a2B = __hfma2(dhB, w2[2][k], a2B);
        }

        // Fold halves to fp32.
        const float x0A = hfold(a0A), x1A = hfold(a1A), x2A = hfold(a2A);
        const float x0B = hfold(a0B), x1B = hfold(a1B), x2B = hfold(a2B);

        // Parity-interleaved butterfly: even lanes carry A, odd lanes carry B.
        // Step off=1 merges the opposite stream; off=2,4 reduce within the
        // parity class. Exact fp32.
        const bool odd = (lane & 1);
        float t0 = odd ? x0B : x0A;
        float u0 = odd ? x0A : x0B;
        float t1 = odd ? x1B : x1A;
        float u1 = odd ? x1A : x1B;
        float t2 = odd ? x2B : x2A;
        float u2 = odd ? x2A : x2B;
        t0 += __shfl_xor_sync(0xFFFFFFFFu, u0, 1);
        t1 += __shfl_xor_sync(0xFFFFFFFFu, u1, 1);
        t2 += __shfl_xor_sync(0xFFFFFFFFu, u2, 1);
#pragma unroll
        for (int off = 2; off <= 4; off <<= 1) {
            t0 += __shfl_xor_sync(0xFFFFFFFFu, t0, off);
            t1 += __shfl_xor_sync(0xFFFFFFFFu, t1, off);
            t2 += __shfl_xor_sync(0xFFFFFFFFu, t2, off);
        }
        // Even lane of group g holds A_g sums; odd lane holds B_g sums.

        // Route: output lane L (0..7) takes edge L = (A_g for L<4, B_g for
        // L>=4), i.e. source lane 8*(L&3) + (L>=4 ? 1 : 0).
        const int src = ((lane & 3) << 3) | ((lane & 4) >> 2);
        const float y0 = __shfl_sync(0xFFFFFFFFu, t0, src);
        const float y1 = __shfl_sync(0xFFFFFFFFu, t1, src);
        const float y2 = __shfl_sync(0xFFFFFFFFu, t2, src);

        const float h0 = fmaxf(y0 + ba0, 0.f);
        const float h1 = fmaxf(y1 + ba1, 0.f);
        const float h2 = fmaxf(y2 + ba2, 0.f);
        const float z  = h0 * wb0 + h1 * wb1 + h2 * wb2 + bbv;
        const float r  = __fdividef(1.0f, 1.0f + __expf(-z));
        if (lane < 8) outp[si * 8 + lane] = r;

        si = sn;
        sA = sAn; dA = dAn; sB = sBn; dB = dBn;
    }
}

extern "C" void kernel_launch(void* const* d_in, const int* in_sizes, int n_in,
                              void* d_out, int out_size)
{
    const float* x  = (const float*)d_in[0];
    const void*  ei = d_in[1];
    const float* Wa = (const float*)d_in[2];
    const float* ba = (const float*)d_in[3];
    const float* Wb = (const float*)d_in[4];
    const float* bb = (const float*)d_in[5];
    float* out = (float*)d_out;

    convert_x_kernel<<<(N_NODES * N_FEAT / 4 + 255) / 256, 256>>>(x, (const int*)ei);

    dim3 grid(448, N_POWERS, 1);
    dim3 block(256, 1, 1);
    adj_learn_kernel<<<grid, block>>>(ei, Wa, ba, Wb, bb, out);
}

// round 9
// speedup vs baseline: 1.1481x; 1.0278x over previous
#include <cuda_runtime.h>
#include <cuda_fp16.h>

#define N_NODES 50000
#define N_FEAT  128
#define N_EDGES 600000
#define N_POWERS 3

// fp16 staging copy of x (halves gather traffic + L1 wavefronts).
__device__ __half g_x16[(size_t)N_NODES * N_FEAT];

// 1 if edge_index is genuinely int64 on device, 0 if int32 (JAX x64-off).
__device__ int g_idx_is64;

__global__ void __launch_bounds__(256)
convert_x_kernel(const float* __restrict__ x, const int* __restrict__ ei32)
{
    if (blockIdx.x == 0 && threadIdx.x == 0) {
        int all_zero = 1;
#pragma unroll
        for (int k = 1; k < 256; k += 2) all_zero &= (ei32[k] == 0);
        g_idx_is64 = all_zero;
    }
    const int i = (blockIdx.x * blockDim.x + threadIdx.x) * 4;
    if (i < N_NODES * N_FEAT) {
        const float4 v = *reinterpret_cast<const float4*>(x + i);
        __half2 h0 = __floats2half2_rn(v.x, v.y);
        __half2 h1 = __floats2half2_rn(v.z, v.w);
        uint2 packed;
        packed.x = *reinterpret_cast<unsigned*>(&h0);
        packed.y = *reinterpret_cast<unsigned*>(&h1);
        *reinterpret_cast<uint2*>(&g_x16[i]) = packed;
    }
}

// abs via sign-mask (LOP3 on alu pipe instead of HABS2 on fma pipe).
static __device__ __forceinline__ __half2 habs2_and(__half2 v) {
    unsigned u = *reinterpret_cast<unsigned*>(&v) & 0x7FFF7FFFu;
    return *reinterpret_cast<__half2*>(&u);
}

// Fold half2 -> float (sum of both halves).
static __device__ __forceinline__ float hfold(__half2 a) {
    return __low2float(__hadd2(a, __lowhigh2highlow(a)));
}

// 8 lanes per edge, 8 edges per warp-iteration. Group g (0..3) handles the
// adjacent edge pair (2g, 2g+1) = streams (A, B), so indices load as int2 /
// longlong2. Lane l owns features [8l,8l+8) (chunk fA) and [64+8l,+8) (fB);
// each warp LDG.128 covers exactly one 128B line per edge-row.
// Two-phase register reuse: load the 4 fA-chunk rows (16 regs), FMA them,
// then reuse the same registers for the fB chunks -> fits 64 regs ->
// 4 CTAs/SM. Layer-1 in half2 HFMA2; fp32 parity butterfly (9 SHFL);
// merged epilogue, MUFU sigmoid, one coalesced 32B store.
__global__ void __launch_bounds__(256, 4)
adj_learn_kernel(const void* __restrict__ edge_index_raw,
                 const float* __restrict__ Wa,
                 const float* __restrict__ ba,
                 const float* __restrict__ Wb,
                 const float* __restrict__ bb,
                 float* __restrict__ out)
{
    const int p    = blockIdx.y;
    const int lane = threadIdx.x & 31;
    const int l    = lane & 7;        // lane within edge-group
    const int g    = lane >> 3;       // edge-pair slot 0..3
    const int warp = threadIdx.x >> 5;
    const int warps_per_block = blockDim.x >> 5;
    const int gwarp  = blockIdx.x * warps_per_block + warp;
    const int nwarps = gridDim.x * warps_per_block;

    const int is64 = g_idx_is64;

    const int fA = l * 8;
    const int fB = 64 + l * 8;

    // Per-lane weights: half2 feature-pairs, k=0..3 -> chunk fA, k=4..7 -> fB.
    const float* Wap = Wa + (size_t)p * (N_FEAT * 3);
    __half2 w2[3][8];
#pragma unroll
    for (int k = 0; k < 4; ++k) {
#pragma unroll
        for (int h = 0; h < 3; ++h) {
            w2[h][k]     = __floats2half2_rn(Wap[(fA + 2 * k) * 3 + h],
                                             Wap[(fA + 2 * k + 1) * 3 + h]);
            w2[h][k + 4] = __floats2half2_rn(Wap[(fB + 2 * k) * 3 + h],
                                             Wap[(fB + 2 * k + 1) * 3 + h]);
        }
    }
    const float ba0 = ba[p * 3 + 0];
    const float ba1 = ba[p * 3 + 1];
    const float ba2 = ba[p * 3 + 2];
    const float wb0 = Wb[p * 3 + 0];
    const float wb1 = Wb[p * 3 + 1];
    const float wb2 = Wb[p * 3 + 2];
    const float bbv = bb[p];

    const int*       ei32 = (const int*)edge_index_raw;
    const long long* ei64 = (const long long*)edge_index_raw;
    const size_t src_base = (size_t)p * 2 * N_EDGES;
    const size_t dst_base = src_base + N_EDGES;
    float* outp = out + (size_t)p * N_EDGES;

    const int n_sup = N_EDGES / 8;    // 75000 super-groups of 8 edges

    for (int si = gwarp; si < n_sup; si += nwarps) {
        // Indices for edge pair (2g, 2g+1): one vector load each for src/dst.
        int sA, sB, dA, dB;
        if (is64) {
            const longlong2 s2 = *reinterpret_cast<const longlong2*>(&ei64[src_base + si * 8 + 2 * g]);
            const longlong2 d2 = *reinterpret_cast<const longlong2*>(&ei64[dst_base + si * 8 + 2 * g]);
            sA = (int)s2.x; sB = (int)s2.y;
            dA = (int)d2.x; dB = (int)d2.y;
        } else {
            const int2 s2 = *reinterpret_cast<const int2*>(&ei32[src_base + si * 8 + 2 * g]);
            const int2 d2 = *reinterpret_cast<const int2*>(&ei32[dst_base + si * 8 + 2 * g]);
            sA = s2.x; sB = s2.y;
            dA = d2.x; dB = d2.y;
        }

        const __half* rjA = &g_x16[(size_t)sA * N_FEAT];
        const __half* riA = &g_x16[(size_t)dA * N_FEAT];
        const __half* rjB = &g_x16[(size_t)sB * N_FEAT];
        const __half* riB = &g_x16[(size_t)dB * N_FEAT];

        __half2 a0A = __float2half2_rn(0.f), a1A = a0A, a2A = a0A;
        __half2 a0B = a0A, a1B = a0A, a2B = a0A;

        // ---- Phase 1: fA chunks of all 4 rows (16 data regs) ----
        {
            __half2 jvA[4], ivA[4], jvB[4], ivB[4];
            *reinterpret_cast<uint4*>(jvA) = *reinterpret_cast<const uint4*>(rjA + fA);
            *reinterpret_cast<uint4*>(ivA) = *reinterpret_cast<const uint4*>(riA + fA);
            *reinterpret_cast<uint4*>(jvB) = *reinterpret_cast<const uint4*>(rjB + fA);
            *reinterpret_cast<uint4*>(ivB) = *reinterpret_cast<const uint4*>(riB + fA);
#pragma unroll
            for (int k = 0; k < 4; ++k) {
                const __half2 dhA = habs2_and(__hsub2(jvA[k], ivA[k]));
                const __half2 dhB = habs2_and(__hsub2(jvB[k], ivB[k]));
                a0A = __hfma2(dhA, w2[0][k], a0A);
                a0B = __hfma2(dhB, w2[0][k], a0B);
                a1A = __hfma2(dhA, w2[1][k], a1A);
                a1B = __hfma2(dhB, w2[1][k], a1B);
                a2A = __hfma2(dhA, w2[2][k], a2A);
                a2B = __hfma2(dhB, w2[2][k], a2B);
            }
        }
        // ---- Phase 2: fB chunks (same registers reused) ----
        {
            __half2 jvA[4], ivA[4], jvB[4], ivB[4];
            *reinterpret_cast<uint4*>(jvA) = *reinterpret_cast<const uint4*>(rjA + fB);
            *reinterpret_cast<uint4*>(ivA) = *reinterpret_cast<const uint4*>(riA + fB);
            *reinterpret_cast<uint4*>(jvB) = *reinterpret_cast<const uint4*>(rjB + fB);
            *reinterpret_cast<uint4*>(ivB) = *reinterpret_cast<const uint4*>(riB + fB);
#pragma unroll
            for (int k = 0; k < 4; ++k) {
                const __half2 dhA = habs2_and(__hsub2(jvA[k], ivA[k]));
                const __half2 dhB = habs2_and(__hsub2(jvB[k], ivB[k]));
                a0A = __hfma2(dhA, w2[0][k + 4], a0A);
                a0B = __hfma2(dhB, w2[0][k + 4], a0B);
                a1A = __hfma2(dhA, w2[1][k + 4], a1A);
                a1B = __hfma2(dhB, w2[1][k + 4], a1B);
                a2A = __hfma2(dhA, w2[2][k + 4], a2A);
                a2B = __hfma2(dhB, w2[2][k + 4], a2B);
            }
        }

        // Fold halves to fp32.
        const float x0A = hfold(a0A), x1A = hfold(a1A), x2A = hfold(a2A);
        const float x0B = hfold(a0B), x1B = hfold(a1B), x2B = hfold(a2B);

        // Parity-interleaved butterfly: even lanes carry A, odd carry B.
        const bool odd = (lane & 1);
        float t0 = odd ? x0B : x0A;
        float u0 = odd ? x0A : x0B;
        float t1 = odd ? x1B : x1A;
        float u1 = odd ? x1A : x1B;
        float t2 = odd ? x2B : x2A;
        float u2 = odd ? x2A : x2B;
        t0 += __shfl_xor_sync(0xFFFFFFFFu, u0, 1);
        t1 += __shfl_xor_sync(0xFFFFFFFFu, u1, 1);
        t2 += __shfl_xor_sync(0xFFFFFFFFu, u2, 1);
#pragma unroll
        for (int off = 2; off <= 4; off <<= 1) {
            t0 += __shfl_xor_sync(0xFFFFFFFFu, t0, off);
            t1 += __shfl_xor_sync(0xFFFFFFFFu, t1, off);
            t2 += __shfl_xor_sync(0xFFFFFFFFu, t2, off);
        }
        // Even lane of group g holds edge 2g sums; odd lane holds edge 2g+1.

        // Output lane L (0..7) takes edge L: source lane ((L>>1)<<3)|(L&1).
        const int src = ((lane & 6) << 2) | (lane & 1);
        const float y0 = __shfl_sync(0xFFFFFFFFu, t0, src);
        const float y1 = __shfl_sync(0xFFFFFFFFu, t1, src);
        const float y2 = __shfl_sync(0xFFFFFFFFu, t2, src);

        const float h0 = fmaxf(y0 + ba0, 0.f);
        const float h1 = fmaxf(y1 + ba1, 0.f);
        const float h2 = fmaxf(y2 + ba2, 0.f);
        const float z  = h0 * wb0 + h1 * wb1 + h2 * wb2 + bbv;
        const float r  = __fdividef(1.0f, 1.0f + __expf(-z));
        if (lane < 8) outp[si * 8 + lane] = r;
    }
}

extern "C" void kernel_launch(void* const* d_in, const int* in_sizes, int n_in,
                              void* d_out, int out_size)
{
    const float* x  = (const float*)d_in[0];
    const void*  ei = d_in[1];
    const float* Wa = (const float*)d_in[2];
    const float* ba = (const float*)d_in[3];
    const float* Wb = (const float*)d_in[4];
    const float* bb = (const float*)d_in[5];
    float* out = (float*)d_out;

    convert_x_kernel<<<(N_NODES * N_FEAT / 4 + 255) / 256, 256>>>(x, (const int*)ei);

    // 591 CTAs ~= one wave at 4 CTAs/SM x 148 SMs.
    dim3 grid(197, N_POWERS, 1);
    dim3 block(256, 1, 1);
    adj_learn_kernel<<<grid, block>>>(ei, Wa, ba, Wb, bb, out);
}